// round 12
// baseline (speedup 1.0000x reference)
#include <cuda_runtime.h>
#include <math.h>
#include <stdint.h>

#define BB 4
#define NN 4096
#define DD 1024
#define EE 64
#define CAP 80
#define NTOK (BB*NN)            // 16384
#define EC (EE*CAP)             // 5120
#define COMBINE_OFF ((size_t)NTOK*(size_t)EC)   // 83886080

#define GEMM_BLOCKS 256
#define FILL_BLOCKS 2560
#define FILL_V4_PER_BLOCK 16384    // 41,943,040 float4 / 2560 blocks
#define FILL_V4_PER_THREAD 64      // / 256 threads

// Eigen/XLA-CPU vectorized exp clamps its input at ln(FLT_MIN)
#define EXP_CLAMP_LO (-87.33654785156250f)

// ---------------- scratch (no allocs allowed) ----------------
__device__ int    g_idx12 [NTOK];            // idx1 | idx2<<8
__device__ float2 g_gate  [NTOK];            // (g1, g2)
__device__ double g_psum  [BB*EE];           // sum of probs per (b,e)
__device__ double g_bal;
__device__ double g_zsum;                    // sum of lse over all tokens
__device__ int    g_cnt = 0;                 // scan-block completion counter

// Emulate XLA:CPU FTZ: flush f32 denormals to +0 (bit-level, compiler-proof).
__device__ __forceinline__ float ftz(float v) {
    unsigned u = __float_as_uint(v);
    return ((u & 0x7F800000u) == 0u) ? 0.0f : v;
}

// ---------------- mega-kernel: GEMM+softmax+top2 blocks & zero-fill blocks ----------------
__global__ void gemm_fill_kernel(const float* __restrict__ x,
                                 const float* __restrict__ w,
                                 float* __restrict__ out) {
    int tid = threadIdx.x;

    if (blockIdx.x >= GEMM_BLOCKS) {
        // ---------------- fill branch: stream 671MB of zeros ----------------
        float4* ov = (float4*)out;
        size_t base = (size_t)(blockIdx.x - GEMM_BLOCKS) * FILL_V4_PER_BLOCK + tid;
        const float4 z4 = make_float4(0.f, 0.f, 0.f, 0.f);
#pragma unroll 8
        for (int i = 0; i < FILL_V4_PER_THREAD; i++)
            __stcs(&ov[base + (size_t)i * 256], z4);
        return;
    }

    // ---------------- GEMM branch: 64 tok x 64 exp, reg-double-buffered ----------------
    __shared__ float xs[64][64];   // k-tiles; reused as logits in epilogue
    __shared__ float ws[64][64];
    __shared__ float accs[64];     // per-block expert prob sums

    if (blockIdx.x == 0) {                 // re-zero per replay, before consumers run
        if (tid < BB*EE) g_psum[tid] = 0.0;
        if (tid == 0) { g_bal = 0.0; g_zsum = 0.0; }
    }

    int tx = tid & 15;
    int ty = tid >> 4;
    int tok0 = blockIdx.x * 64;

    float4 rx[4], rw[4];
#pragma unroll
    for (int r = 0; r < 4; r++) {
        int f = tid + 256 * r;
        int row = f >> 4, q = f & 15;
        rx[r] = *(const float4*)(x + (size_t)(tok0 + row) * DD + q * 4);
        rw[r] = *(const float4*)(w + (size_t)row * EE + q * 4);
    }

    float acc[4][4];
#pragma unroll
    for (int i = 0; i < 4; i++)
#pragma unroll
        for (int j = 0; j < 4; j++) acc[i][j] = 0.f;

    for (int t = 0; t < DD / 64; t++) {
        __syncthreads();
#pragma unroll
        for (int r = 0; r < 4; r++) {
            int f = tid + 256 * r;
            int row = f >> 4, q = f & 15;
            *(float4*)&xs[row][q * 4] = rx[r];
            *(float4*)&ws[row][q * 4] = rw[r];
        }
        __syncthreads();

        if (t + 1 < DD / 64) {             // prefetch next tile; consumed post-FMA
            int kk = (t + 1) * 64;
#pragma unroll
            for (int r = 0; r < 4; r++) {
                int f = tid + 256 * r;
                int row = f >> 4, q = f & 15;
                rx[r] = *(const float4*)(x + (size_t)(tok0 + row) * DD + kk + q * 4);
                rw[r] = *(const float4*)(w + (size_t)(kk + row) * EE + q * 4);
            }
        }

#pragma unroll 16
        for (int k = 0; k < 64; k++) {
            float4 wv = *(float4*)&ws[k][tx * 4];
            float x0 = xs[ty * 4 + 0][k];
            float x1 = xs[ty * 4 + 1][k];
            float x2 = xs[ty * 4 + 2][k];
            float x3 = xs[ty * 4 + 3][k];
            acc[0][0] += x0 * wv.x; acc[0][1] += x0 * wv.y; acc[0][2] += x0 * wv.z; acc[0][3] += x0 * wv.w;
            acc[1][0] += x1 * wv.x; acc[1][1] += x1 * wv.y; acc[1][2] += x1 * wv.z; acc[1][3] += x1 * wv.w;
            acc[2][0] += x2 * wv.x; acc[2][1] += x2 * wv.y; acc[2][2] += x2 * wv.z; acc[2][3] += x2 * wv.w;
            acc[3][0] += x3 * wv.x; acc[3][1] += x3 * wv.y; acc[3][2] += x3 * wv.z; acc[3][3] += x3 * wv.w;
        }
    }

    // ---------------- epilogue: softmax + top-2 on the 64x64 logits in smem ----------------
    __syncthreads();
#pragma unroll
    for (int i = 0; i < 4; i++)
#pragma unroll
        for (int j = 0; j < 4; j++)
            xs[ty * 4 + i][tx * 4 + j] = acc[i][j];
    if (tid < 64) accs[tid] = 0.f;
    __syncthreads();

    int warp = tid >> 5;
    int lane = tid & 31;
    double zacc = 0.0;

#pragma unroll
    for (int u = 0; u < 8; u++) {
        int tt = warp * 8 + u;             // token within tile
        float v0 = xs[tt][lane];
        float v1 = xs[tt][lane + 32];

        float m = fmaxf(v0, v1);
#pragma unroll
        for (int o = 16; o; o >>= 1) m = fmaxf(m, __shfl_xor_sync(0xffffffffu, m, o));

        float e0 = expf(fmaxf(v0 - m, EXP_CLAMP_LO));
        float e1 = expf(fmaxf(v1 - m, EXP_CLAMP_LO));
        float s = e0 + e1;
#pragma unroll
        for (int o = 16; o; o >>= 1) s += __shfl_xor_sync(0xffffffffu, s, o);

        float p0 = ftz(e0 / s);
        float p1 = ftz(e1 / s);

        atomicAdd(&accs[lane],      p0);
        atomicAdd(&accs[lane + 32], p1);

        unsigned long long k0 = ((unsigned long long)__float_as_uint(p0) << 32) | (unsigned)(63 - lane);
        unsigned long long k1 = ((unsigned long long)__float_as_uint(p1) << 32) | (unsigned)(63 - (lane + 32));

        unsigned long long kt = (k0 > k1) ? k0 : k1;
#pragma unroll
        for (int o = 16; o; o >>= 1) {
            unsigned long long ko = __shfl_xor_sync(0xffffffffu, kt, o);
            if (ko > kt) kt = ko;
        }
        int ri = 63 - (int)(kt & 0x3F);

        unsigned long long q0 = (lane        == ri) ? 0ULL : k0;
        unsigned long long q1 = ((lane + 32) == ri) ? 0ULL : k1;
        unsigned long long kt2 = (q0 > q1) ? q0 : q1;
#pragma unroll
        for (int o = 16; o; o >>= 1) {
            unsigned long long ko = __shfl_xor_sync(0xffffffffu, kt2, o);
            if (ko > kt2) kt2 = ko;
        }
        int ri2 = 63 - (int)(kt2 & 0x3F);

        if (lane == 0) {
            zacc += (double)m + log((double)s);
            float pv1 = __uint_as_float((unsigned)(kt  >> 32));
            float pv2 = __uint_as_float((unsigned)(kt2 >> 32));
            float denom = pv1 + pv2 + 1e-9f;
            g_idx12[tok0 + tt] = ri | (ri2 << 8);
            g_gate[tok0 + tt] = make_float2(ftz(pv1 / denom), ftz(pv2 / denom));
        }
    }

    if (lane == 0) atomicAdd(&g_zsum, zacc);
    __syncthreads();
    if (tid < 64) {
        int b = tok0 >> 12;                // 4096 tokens per batch
        atomicAdd(&g_psum[b * EE + tid], (double)accs[tid]);
    }
}

// ---------------- scan + scatter + finalize (one launch) ----------------
__device__ __forceinline__ int block_scan_incl(int v, int* sh, int tid, int* total) {
    __syncthreads();
    sh[tid] = v;
    __syncthreads();
#pragma unroll
    for (int o = 1; o < 256; o <<= 1) {
        int t = (tid >= o) ? sh[tid - o] : 0;
        __syncthreads();
        sh[tid] += t;
        __syncthreads();
    }
    int incl = sh[tid];
    *total = sh[255];
    return incl;
}

__global__ void scan_scatter_kernel(float* __restrict__ out) {
    __shared__ int sh[256];
    int b = blockIdx.x >> 6;
    int e = blockIdx.x & 63;
    int tid = threadIdx.x;
    int base = b * NN;
    int n0 = tid * 16;

    int idx[16];
#pragma unroll
    for (int q = 0; q < 4; q++) {
        int4 v = *(const int4*)&g_idx12[base + n0 + q * 4];
        idx[q*4+0] = v.x; idx[q*4+1] = v.y; idx[q*4+2] = v.z; idx[q*4+3] = v.w;
    }

    int c1 = 0, c2 = 0;
    unsigned m1bits = 0, m2bits = 0;
#pragma unroll
    for (int j = 0; j < 16; j++) {
        if ((idx[j] & 0xFF) == e) { c1++; m1bits |= (1u << j); }
        if ((idx[j] >> 8)   == e) { c2++; m2bits |= (1u << j); }
    }

    int tot1, tot2;
    int incl1 = block_scan_incl(c1, sh, tid, &tot1);
    int incl2 = block_scan_incl(c2, sh, tid, &tot2);
    (void)tot2;

    int off1 = incl1 - c1;
    int off2 = incl2 - c2;
#pragma unroll
    for (int j = 0; j < 16; j++) {
        int tok = base + n0 + j;
        if ((m1bits >> j) & 1u) {
            if (off1 < CAP) {
                float v = g_gate[tok].x;
                if (__float_as_int(v) != 0) {
                    size_t o1 = (size_t)tok * EC + e * CAP + off1;
                    out[o1] = 1.f;
                    out[COMBINE_OFF + o1] = v;
                }
            }
            off1++;
        }
        if ((m2bits >> j) & 1u) {
            if (off2 < CAP) {
                float v = g_gate[tok].y;
                if (__float_as_int(v) != 0) {
                    size_t o2 = (size_t)tok * EC + e * CAP + off2;
                    out[o2] = 1.f;
                    out[COMBINE_OFF + o2] = v;
                }
            }
            off2++;
        }
    }

    if (tid == 0) {
        double part = (g_psum[b * EE + e] / (double)NN) * ((double)tot1 / (double)NN);
        atomicAdd(&g_bal, part);
        __threadfence();
        int done = atomicAdd(&g_cnt, 1);
        if ((done & 255) == 255) {         // last of the 256 blocks this launch
            __threadfence();
            out[2 * COMBINE_OFF]     = (float)(g_bal * (double)EE / (double)BB);
            out[2 * COMBINE_OFF + 1] = (float)(g_zsum / (double)BB);
        }
    }
}

extern "C" void kernel_launch(void* const* d_in, const int* in_sizes, int n_in,
                              void* d_out, int out_size) {
    const float* x = (const float*)d_in[0];
    const float* w = (const float*)d_in[1];
    float* out = (float*)d_out;

    gemm_fill_kernel<<<GEMM_BLOCKS + FILL_BLOCKS, 256>>>(x, w, out);
    scan_scatter_kernel<<<BB * EE, 256>>>(out);
}